// round 7
// baseline (speedup 1.0000x reference)
#include <cuda_runtime.h>
#include <cuda_fp16.h>

#define NN 100000
#define NE 1200000
#define NF 64
#define NH 256
#define NC 40
#define NITER 8
#define NSCAN 196                     // ceil(NN/512) scan tiles

// ---------------- scratch (device globals; no allocation) ----------------
__device__ int   g_cnt[NN];
__device__ float g_dinv[NN];
__device__ int   g_rowptr[NN + 1];
__device__ int   g_cursor[NN];
__device__ unsigned long long g_tile_state[NSCAN];  // (status<<32)|sum; 1=agg,2=prefix
__device__ int   g_tile_counter;
__device__ __align__(16) int2    g_csr[NE];                      // {col, w bits}
// h0..h8 in fp16: (9 * 100000 * 32) half2 = 115 MB. Row = 32 half2 = 128 B.
__device__ __align__(16) __half2 g_hh[(NITER + 1) * (size_t)NN * (NF / 2)];

__device__ __forceinline__ int clampN(int v) {
    return min(max(v, 0), NN - 1);
}

// ---------------- L1: histogram (+ reset scan state for this run) ----------
// Invariant: g_cnt is zero on entry (zero-initialized at load; re-zeroed by
// k_scatter at the end of every run -> graph replays see zeros).
__global__ void k_hist(const int* __restrict__ ei) {
    int e = blockIdx.x * blockDim.x + threadIdx.x;
    if (e < NE) atomicAdd(&g_cnt[clampN(ei[e])], 1);
    if (e < NSCAN) g_tile_state[e] = 0ULL;
    if (e == NSCAN) g_tile_counter = 0;
}

// ---------------- L2: decoupled-lookback scan + dinv + h0 init -------------
// blocks [0, NSCAN): scan tiles (dynamic tile ids -> in-order acquisition)
// blocks [NSCAN, ..): h0 = 0.5*x  (fp32 -> fp16 storage)
__global__ void __launch_bounds__(512) k_scan_init(const float* __restrict__ x) {
    if (blockIdx.x < NSCAN) {
        __shared__ int s[512];
        __shared__ int stile;
        __shared__ int sprefix;
        int t = threadIdx.x;
        if (t == 0) stile = atomicAdd(&g_tile_counter, 1);
        __syncthreads();
        int tile = stile;
        int i = tile * 512 + t;
        int v = (i < NN) ? g_cnt[i] : 0;
        if (i < NN) g_dinv[i] = rsqrtf((float)(v + 1));
        s[t] = v;
        __syncthreads();
        for (int off = 1; off < 512; off <<= 1) {
            int add = (t >= off) ? s[t - off] : 0;
            __syncthreads();
            s[t] += add;
            __syncthreads();
        }
        int incl = s[t];
        int agg  = s[511];
        if (t == 0) {
            if (tile == 0) {
                atomicExch(&g_tile_state[0], (2ULL << 32) | (unsigned)agg);
                sprefix = 0;
            } else {
                atomicExch(&g_tile_state[tile], (1ULL << 32) | (unsigned)agg);
                int pre = 0;
                for (int p = tile - 1; p >= 0; ) {
                    unsigned long long st;
                    do { st = atomicAdd(&g_tile_state[p], 0ULL); } while ((st >> 32) == 0);
                    pre += (int)(unsigned)st;
                    if ((st >> 32) == 2ULL) break;
                    p--;
                }
                atomicExch(&g_tile_state[tile], (2ULL << 32) | (unsigned)(pre + agg));
                sprefix = pre;
            }
        }
        __syncthreads();
        if (i < NN) {
            int rp = sprefix + incl - v;   // exclusive
            g_rowptr[i] = rp;
            g_cursor[i] = rp;
        }
        if (tile == 0 && t == 0) g_rowptr[NN] = NE;
    } else {
        int i = (blockIdx.x - NSCAN) * 512 + threadIdx.x;   // quad of 4 floats
        if (i < NN * (NF / 4)) {
            float4 v = ((const float4*)x)[i];
            __half2 a = __floats2half2_rn(v.x * 0.5f, v.y * 0.5f);
            __half2 b = __floats2half2_rn(v.z * 0.5f, v.w * 0.5f);
            *(uint2*)&g_hh[(size_t)i * 2] =
                make_uint2(*(unsigned*)&a, *(unsigned*)&b);
        }
    }
}

// ---------------- L3: scatter (+ re-zero g_cnt for next run) ----------------
__global__ void k_scatter(const int* __restrict__ ei) {
    int e = blockIdx.x * blockDim.x + threadIdx.x;
    if (e < NE) {
        int r = clampN(ei[e]);
        int c = clampN(ei[NE + e]);
        int pos = atomicAdd(&g_cursor[r], 1);
        g_csr[pos] = make_int2(c, __float_as_int(g_dinv[r] * g_dinv[c]));
    }
    if (e < NN) g_cnt[e] = 0;
}

// ---------------- SPMM: h_{it+1} = A_norm h_it (fp16 storage, fp32 math) ----
// one warp per row, lane = 2 features (half2 = 4B; warp gather = 128B line)
__global__ void __launch_bounds__(256) k_spmm(int it) {
    const size_t NN32 = (size_t)NN * (NF / 2);
    const __half2* __restrict__ hin = g_hh + (size_t)it * NN32;
    __half2* __restrict__ hout      = g_hh + (size_t)(it + 1) * NN32;

    __shared__ int2 se[8][32];

    int lane = threadIdx.x & 31;
    int wid  = threadIdx.x >> 5;
    int r    = blockIdx.x * 8 + wid;   // NN divisible by 8

    int start = g_rowptr[r];
    int end   = g_rowptr[r + 1];
    float dr  = g_dinv[r];

    float2 hv = __half22float2(__ldg(&hin[(size_t)r * 32 + lane]));
    float dw  = dr * dr;
    // two accumulator pairs to split the FFMA dependency chain
    float2 acc0, acc1;
    acc0.x = dw * hv.x; acc0.y = dw * hv.y;
    acc1.x = 0.f;       acc1.y = 0.f;

    for (int b = start; b < end; b += 32) {
        int idx = b + lane;
        int2 e = make_int2(0, 0);      // w=0 => harmless dummy gather of row 0
        if (idx < end) e = g_csr[idx];
        se[wid][lane] = e;
        __syncwarp();
        int m = min(32, end - b);
#pragma unroll 4
        for (int j = 0; j < m; j++) {
            int2  ej = se[wid][j];
            float wj = __int_as_float(ej.y);
            float2 t = __half22float2(__ldg(&hin[(size_t)ej.x * 32 + lane]));
            if (j & 1) { acc1.x += wj * t.x; acc1.y += wj * t.y; }
            else       { acc0.x += wj * t.x; acc0.y += wj * t.y; }
        }
        __syncwarp();
    }

    hout[(size_t)r * 32 + lane] =
        __floats2half2_rn(acc0.x + acc1.x, acc0.y + acc1.y);
}

// ---------------- fused MLP: out = relu((avg(h)) @ W1 + b1) @ W2 + b2 ------
// block = 32 rows; hid processed in 4 chunks of 64 cols, never materialized.
__global__ void __launch_bounds__(256) k_mlp(const float* __restrict__ W1,
                                             const float* __restrict__ b1,
                                             const float* __restrict__ W2,
                                             const float* __restrict__ b2,
                                             float* __restrict__ out) {
    __shared__ __align__(16) float As[32 * 68];    // 8.7 KB  (padded stride 68)
    __shared__ __align__(16) float W1c[64 * 64];   // 16 KB
    __shared__ __align__(16) float Hs[32 * 68];    // 8.7 KB
    __shared__ __align__(16) float W2cT[40 * 68];  // 10.9 KB (transposed, padded)
    __shared__ float sb1[64];

    int tid = threadIdx.x;
    int rb  = blockIdx.x * 32;        // NN divisible by 32

    // As = (1/9) * sum_{b=0..8} h_b  [32 x 64], fp32 accumulation
    const float inv = 1.0f / (NITER + 1);
    const size_t NN32 = (size_t)NN * (NF / 2);
    for (int l = tid; l < 32 * 16; l += 256) {   // quads of 4 feats
        int rr = l >> 4, q = l & 15;
        float4 s = make_float4(0.f, 0.f, 0.f, 0.f);
#pragma unroll
        for (int b = 0; b <= NITER; b++) {
            const uint2* hb = (const uint2*)(g_hh + (size_t)b * NN32);
            uint2 v = __ldg(&hb[(size_t)(rb + rr) * 16 + q]);
            float2 f0 = __half22float2(*(__half2*)&v.x);
            float2 f1 = __half22float2(*(__half2*)&v.y);
            s.x += f0.x; s.y += f0.y; s.z += f1.x; s.w += f1.y;
        }
        s.x *= inv; s.y *= inv; s.z *= inv; s.w *= inv;
        *(float4*)&As[rr * 68 + q * 4] = s;
    }

    int tx  = tid & 15, ty = tid >> 4;   // hid-compute mapping: 2 rows x 4 cols
    int row = tid >> 3, cg = tid & 7;    // gemm2 mapping: 1 row x 5 cols
    float acc5[5] = {0.f, 0.f, 0.f, 0.f, 0.f};

    for (int c = 0; c < 4; c++) {
        __syncthreads();   // Hs of prev chunk fully consumed; safe to reload
        // W1 chunk [64 x 64]
        for (int l = tid; l < 64 * 16; l += 256) {
            int kk = l >> 4, j4 = l & 15;
            *(float4*)&W1c[kk * 64 + j4 * 4] =
                __ldg((const float4*)&W1[kk * NH + c * 64 + j4 * 4]);
        }
        // W2 chunk transposed: W2[(c*64+k)*40 + cc] -> W2cT[cc*68 + k]
        for (int l = tid; l < 64 * 40; l += 256) {
            int kk = l / 40, cc = l - kk * 40;
            W2cT[cc * 68 + kk] = __ldg(&W2[(c * 64 + kk) * NC + cc]);
        }
        if (tid < 64) sb1[tid] = __ldg(&b1[c * 64 + tid]);
        __syncthreads();

        // hid tile in regs: rows ty*2+{0,1}, cols tx*4..tx*4+3, K=64
        float4 hh0 = make_float4(0.f, 0.f, 0.f, 0.f);
        float4 hh1 = make_float4(0.f, 0.f, 0.f, 0.f);
#pragma unroll
        for (int k = 0; k < 64; k++) {
            float4 w = *(const float4*)&W1c[k * 64 + tx * 4];
            float a0 = As[(ty * 2 + 0) * 68 + k];
            float a1 = As[(ty * 2 + 1) * 68 + k];
            hh0.x += a0 * w.x; hh0.y += a0 * w.y; hh0.z += a0 * w.z; hh0.w += a0 * w.w;
            hh1.x += a1 * w.x; hh1.y += a1 * w.y; hh1.z += a1 * w.z; hh1.w += a1 * w.w;
        }
        float bx = sb1[tx * 4], by = sb1[tx * 4 + 1],
              bz = sb1[tx * 4 + 2], bw = sb1[tx * 4 + 3];
        float4 o0, o1;
        o0.x = fmaxf(hh0.x + bx, 0.f); o0.y = fmaxf(hh0.y + by, 0.f);
        o0.z = fmaxf(hh0.z + bz, 0.f); o0.w = fmaxf(hh0.w + bw, 0.f);
        o1.x = fmaxf(hh1.x + bx, 0.f); o1.y = fmaxf(hh1.y + by, 0.f);
        o1.z = fmaxf(hh1.z + bz, 0.f); o1.w = fmaxf(hh1.w + bw, 0.f);
        *(float4*)&Hs[(ty * 2 + 0) * 68 + tx * 4] = o0;
        *(float4*)&Hs[(ty * 2 + 1) * 68 + tx * 4] = o1;
        __syncthreads();

        // gemm2 partial: acc5 += Hs[row, :64] . W2cT[col, :64]
#pragma unroll
        for (int k4 = 0; k4 < 16; k4++) {
            float4 h = *(const float4*)&Hs[row * 68 + k4 * 4];
#pragma unroll
            for (int j = 0; j < 5; j++) {
                float4 w = *(const float4*)&W2cT[(cg * 5 + j) * 68 + k4 * 4];
                acc5[j] += h.x * w.x + h.y * w.y + h.z * w.z + h.w * w.w;
            }
        }
    }

#pragma unroll
    for (int j = 0; j < 5; j++)
        out[(size_t)(rb + row) * NC + cg * 5 + j] = acc5[j] + __ldg(&b2[cg * 5 + j]);
}

// ---------------- launch ----------------
extern "C" void kernel_launch(void* const* d_in, const int* in_sizes, int n_in,
                              void* d_out, int out_size) {
    const float* x   = (const float*)d_in[0];
    const int*   ei  = (const int*)d_in[1];   // int32 (JAX demotes int64)
    const float* W1  = (const float*)d_in[2];
    const float* b1  = (const float*)d_in[3];
    const float* W2  = (const float*)d_in[4];
    const float* b2  = (const float*)d_in[5];
    float*       out = (float*)d_out;

    int init_blocks = (NN * (NF / 4) + 511) / 512;   // 3125

    k_hist<<<(NE + 255) / 256, 256>>>(ei);                     // launch 1
    k_scan_init<<<NSCAN + init_blocks, 512>>>(x);              // launch 2
    k_scatter<<<(NE + 255) / 256, 256>>>(ei);                  // launch 3

    for (int it = 0; it < NITER; it++)                         // launches 4..11
        k_spmm<<<NN / 8, 256>>>(it);

    k_mlp<<<NN / 32, 256>>>(W1, b1, W2, b2, out);              // launch 12
}

// round 9
// speedup vs baseline: 1.0284x; 1.0284x over previous
// R9 = R8 resubmitted verbatim (R8 bench was a broker infra failure; the
// HFMA2 experiment was never measured).
#include <cuda_runtime.h>
#include <cuda_fp16.h>

#define NN 100000
#define NE 1200000
#define NF 64
#define NH 256
#define NC 40
#define NITER 8
#define NSCAN 196                     // ceil(NN/512) scan tiles

// ---------------- scratch (device globals; no allocation) ----------------
__device__ int   g_cnt[NN];
__device__ float g_dinv[NN];
__device__ int   g_rowptr[NN + 1];
__device__ int   g_cursor[NN];
__device__ unsigned long long g_tile_state[NSCAN];  // (status<<32)|sum; 1=agg,2=prefix
__device__ int   g_tile_counter;
__device__ __align__(16) int2    g_csr[NE];         // {col*32, w as half2 bits}
// h0..h8 in fp16: (9 * 100000 * 32) half2 = 115 MB. Row = 32 half2 = 128 B.
__device__ __align__(16) __half2 g_hh[(NITER + 1) * (size_t)NN * (NF / 2)];

__device__ __forceinline__ int clampN(int v) {
    return min(max(v, 0), NN - 1);
}

// ---------------- L1: histogram (+ reset scan state for this run) ----------
// Invariant: g_cnt is zero on entry (zero-initialized at load; re-zeroed by
// k_scatter at the end of every run -> graph replays see zeros).
__global__ void k_hist(const int* __restrict__ ei) {
    int e = blockIdx.x * blockDim.x + threadIdx.x;
    if (e < NE) atomicAdd(&g_cnt[clampN(ei[e])], 1);
    if (e < NSCAN) g_tile_state[e] = 0ULL;
    if (e == NSCAN) g_tile_counter = 0;
}

// ---------------- L2: decoupled-lookback scan + dinv + h0 init -------------
// blocks [0, NSCAN): scan tiles (dynamic tile ids -> in-order acquisition)
// blocks [NSCAN, ..): h0 = 0.5*x  (fp32 -> fp16 storage)
__global__ void __launch_bounds__(512) k_scan_init(const float* __restrict__ x) {
    if (blockIdx.x < NSCAN) {
        __shared__ int s[512];
        __shared__ int stile;
        __shared__ int sprefix;
        int t = threadIdx.x;
        if (t == 0) stile = atomicAdd(&g_tile_counter, 1);
        __syncthreads();
        int tile = stile;
        int i = tile * 512 + t;
        int v = (i < NN) ? g_cnt[i] : 0;
        if (i < NN) g_dinv[i] = rsqrtf((float)(v + 1));
        s[t] = v;
        __syncthreads();
        for (int off = 1; off < 512; off <<= 1) {
            int add = (t >= off) ? s[t - off] : 0;
            __syncthreads();
            s[t] += add;
            __syncthreads();
        }
        int incl = s[t];
        int agg  = s[511];
        if (t == 0) {
            if (tile == 0) {
                atomicExch(&g_tile_state[0], (2ULL << 32) | (unsigned)agg);
                sprefix = 0;
            } else {
                atomicExch(&g_tile_state[tile], (1ULL << 32) | (unsigned)agg);
                int pre = 0;
                for (int p = tile - 1; p >= 0; ) {
                    unsigned long long st;
                    do { st = atomicAdd(&g_tile_state[p], 0ULL); } while ((st >> 32) == 0);
                    pre += (int)(unsigned)st;
                    if ((st >> 32) == 2ULL) break;
                    p--;
                }
                atomicExch(&g_tile_state[tile], (2ULL << 32) | (unsigned)(pre + agg));
                sprefix = pre;
            }
        }
        __syncthreads();
        if (i < NN) {
            int rp = sprefix + incl - v;   // exclusive
            g_rowptr[i] = rp;
            g_cursor[i] = rp;
        }
        if (tile == 0 && t == 0) g_rowptr[NN] = NE;
    } else {
        int i = (blockIdx.x - NSCAN) * 512 + threadIdx.x;   // quad of 4 floats
        if (i < NN * (NF / 4)) {
            float4 v = ((const float4*)x)[i];
            __half2 a = __floats2half2_rn(v.x * 0.5f, v.y * 0.5f);
            __half2 b = __floats2half2_rn(v.z * 0.5f, v.w * 0.5f);
            *(uint2*)&g_hh[(size_t)i * 2] =
                make_uint2(*(unsigned*)&a, *(unsigned*)&b);
        }
    }
}

// ---------------- L3: scatter (+ re-zero g_cnt for next run) ----------------
// csr entry: {col*32 (half2-element offset of the row), weight as half2 bits}
__global__ void k_scatter(const int* __restrict__ ei) {
    int e = blockIdx.x * blockDim.x + threadIdx.x;
    if (e < NE) {
        int r = clampN(ei[e]);
        int c = clampN(ei[NE + e]);
        int pos = atomicAdd(&g_cursor[r], 1);
        __half2 wh = __float2half2_rn(g_dinv[r] * g_dinv[c]);
        g_csr[pos] = make_int2(c * 32, *reinterpret_cast<int*>(&wh));
    }
    if (e < NN) g_cnt[e] = 0;
}

// ---------------- SPMM: h_{it+1} = A_norm h_it ------------------------------
// one warp per row, lane = 2 features. HFMA2 accumulation (fp16), folded to
// fp32 every 32-edge chunk; diagonal term in fp32. Gather index is a single
// int add (csr stores col*32).
__global__ void __launch_bounds__(256) k_spmm(int it) {
    const size_t NN32 = (size_t)NN * (NF / 2);
    const __half2* __restrict__ hin = g_hh + (size_t)it * NN32;
    __half2* __restrict__ hout      = g_hh + (size_t)(it + 1) * NN32;

    __shared__ int2 se[8][32];

    int lane = threadIdx.x & 31;
    int wid  = threadIdx.x >> 5;
    int r    = blockIdx.x * 8 + wid;   // NN divisible by 8

    int start = g_rowptr[r];
    int end   = g_rowptr[r + 1];
    float dr  = g_dinv[r];

    float2 hv = __half22float2(__ldg(&hin[r * 32 + lane]));
    float dw  = dr * dr;
    float accx = dw * hv.x;
    float accy = dw * hv.y;

    const __half2 zero2 = __float2half2_rn(0.f);

    for (int b = start; b < end; b += 32) {
        int idx = b + lane;
        int2 e = make_int2(0, 0);      // w bits 0 => half2(0,0): harmless dummy
        if (idx < end) e = g_csr[idx];
        se[wid][lane] = e;
        __syncwarp();
        int m = min(32, end - b);
        __half2 h0 = zero2, h1 = zero2;   // two fp16 chains (<=16 adds each)
#pragma unroll 4
        for (int j = 0; j < m; j++) {
            int2    ej = se[wid][j];
            __half2 wj = *reinterpret_cast<__half2*>(&ej.y);
            __half2 t  = __ldg(&hin[ej.x + lane]);
            if (j & 1) h1 = __hfma2(wj, t, h1);
            else       h0 = __hfma2(wj, t, h0);
        }
        __syncwarp();
        float2 f0 = __half22float2(h0);
        float2 f1 = __half22float2(h1);
        accx += f0.x + f1.x;
        accy += f0.y + f1.y;
    }

    hout[r * 32 + lane] = __floats2half2_rn(accx, accy);
}

// ---------------- fused MLP: out = relu((avg(h)) @ W1 + b1) @ W2 + b2 ------
// block = 32 rows; hid processed in 4 chunks of 64 cols, never materialized.
__global__ void __launch_bounds__(256) k_mlp(const float* __restrict__ W1,
                                             const float* __restrict__ b1,
                                             const float* __restrict__ W2,
                                             const float* __restrict__ b2,
                                             float* __restrict__ out) {
    __shared__ __align__(16) float As[32 * 68];    // 8.7 KB  (padded stride 68)
    __shared__ __align__(16) float W1c[64 * 64];   // 16 KB
    __shared__ __align__(16) float Hs[32 * 68];    // 8.7 KB
    __shared__ __align__(16) float W2cT[40 * 68];  // 10.9 KB (transposed, padded)
    __shared__ float sb1[64];

    int tid = threadIdx.x;
    int rb  = blockIdx.x * 32;        // NN divisible by 32

    // As = (1/9) * sum_{b=0..8} h_b  [32 x 64], fp32 accumulation
    const float inv = 1.0f / (NITER + 1);
    const size_t NN32 = (size_t)NN * (NF / 2);
    for (int l = tid; l < 32 * 16; l += 256) {   // quads of 4 feats
        int rr = l >> 4, q = l & 15;
        float4 s = make_float4(0.f, 0.f, 0.f, 0.f);
#pragma unroll
        for (int b = 0; b <= NITER; b++) {
            const uint2* hb = (const uint2*)(g_hh + (size_t)b * NN32);
            uint2 v = __ldg(&hb[(size_t)(rb + rr) * 16 + q]);
            float2 f0 = __half22float2(*(__half2*)&v.x);
            float2 f1 = __half22float2(*(__half2*)&v.y);
            s.x += f0.x; s.y += f0.y; s.z += f1.x; s.w += f1.y;
        }
        s.x *= inv; s.y *= inv; s.z *= inv; s.w *= inv;
        *(float4*)&As[rr * 68 + q * 4] = s;
    }

    int tx  = tid & 15, ty = tid >> 4;   // hid-compute mapping: 2 rows x 4 cols
    int row = tid >> 3, cg = tid & 7;    // gemm2 mapping: 1 row x 5 cols
    float acc5[5] = {0.f, 0.f, 0.f, 0.f, 0.f};

    for (int c = 0; c < 4; c++) {
        __syncthreads();   // Hs of prev chunk fully consumed; safe to reload
        // W1 chunk [64 x 64]
        for (int l = tid; l < 64 * 16; l += 256) {
            int kk = l >> 4, j4 = l & 15;
            *(float4*)&W1c[kk * 64 + j4 * 4] =
                __ldg((const float4*)&W1[kk * NH + c * 64 + j4 * 4]);
        }
        // W2 chunk transposed: W2[(c*64+k)*40 + cc] -> W2cT[cc*68 + k]
        for (int l = tid; l < 64 * 40; l += 256) {
            int kk = l / 40, cc = l - kk * 40;
            W2cT[cc * 68 + kk] = __ldg(&W2[(c * 64 + kk) * NC + cc]);
        }
        if (tid < 64) sb1[tid] = __ldg(&b1[c * 64 + tid]);
        __syncthreads();

        // hid tile in regs: rows ty*2+{0,1}, cols tx*4..tx*4+3, K=64
        float4 hh0 = make_float4(0.f, 0.f, 0.f, 0.f);
        float4 hh1 = make_float4(0.f, 0.f, 0.f, 0.f);
#pragma unroll
        for (int k = 0; k < 64; k++) {
            float4 w = *(const float4*)&W1c[k * 64 + tx * 4];
            float a0 = As[(ty * 2 + 0) * 68 + k];
            float a1 = As[(ty * 2 + 1) * 68 + k];
            hh0.x += a0 * w.x; hh0.y += a0 * w.y; hh0.z += a0 * w.z; hh0.w += a0 * w.w;
            hh1.x += a1 * w.x; hh1.y += a1 * w.y; hh1.z += a1 * w.z; hh1.w += a1 * w.w;
        }
        float bx = sb1[tx * 4], by = sb1[tx * 4 + 1],
              bz = sb1[tx * 4 + 2], bw = sb1[tx * 4 + 3];
        float4 o0, o1;
        o0.x = fmaxf(hh0.x + bx, 0.f); o0.y = fmaxf(hh0.y + by, 0.f);
        o0.z = fmaxf(hh0.z + bz, 0.f); o0.w = fmaxf(hh0.w + bw, 0.f);
        o1.x = fmaxf(hh1.x + bx, 0.f); o1.y = fmaxf(hh1.y + by, 0.f);
        o1.z = fmaxf(hh1.z + bz, 0.f); o1.w = fmaxf(hh1.w + bw, 0.f);
        *(float4*)&Hs[(ty * 2 + 0) * 68 + tx * 4] = o0;
        *(float4*)&Hs[(ty * 2 + 1) * 68 + tx * 4] = o1;
        __syncthreads();

        // gemm2 partial: acc5 += Hs[row, :64] . W2cT[col, :64]
#pragma unroll
        for (int k4 = 0; k4 < 16; k4++) {
            float4 h = *(const float4*)&Hs[row * 68 + k4 * 4];
#pragma unroll
            for (int j = 0; j < 5; j++) {
                float4 w = *(const float4*)&W2cT[(cg * 5 + j) * 68 + k4 * 4];
                acc5[j] += h.x * w.x + h.y * w.y + h.z * w.z + h.w * w.w;
            }
        }
    }

#pragma unroll
    for (int j = 0; j < 5; j++)
        out[(size_t)(rb + row) * NC + cg * 5 + j] = acc5[j] + __ldg(&b2[cg * 5 + j]);
}

// ---------------- launch ----------------
extern "C" void kernel_launch(void* const* d_in, const int* in_sizes, int n_in,
                              void* d_out, int out_size) {
    const float* x   = (const float*)d_in[0];
    const int*   ei  = (const int*)d_in[1];   // int32 (JAX demotes int64)
    const float* W1  = (const float*)d_in[2];
    const float* b1  = (const float*)d_in[3];
    const float* W2  = (const float*)d_in[4];
    const float* b2  = (const float*)d_in[5];
    float*       out = (float*)d_out;

    int init_blocks = (NN * (NF / 4) + 511) / 512;   // 3125

    k_hist<<<(NE + 255) / 256, 256>>>(ei);                     // launch 1
    k_scan_init<<<NSCAN + init_blocks, 512>>>(x);              // launch 2
    k_scatter<<<(NE + 255) / 256, 256>>>(ei);                  // launch 3

    for (int it = 0; it < NITER; it++)                         // launches 4..11
        k_spmm<<<NN / 8, 256>>>(it);

    k_mlp<<<NN / 32, 256>>>(W1, b1, W2, b2, out);              // launch 12
}

// round 10
// speedup vs baseline: 1.1619x; 1.1299x over previous
#include <cuda_runtime.h>
#include <cuda_fp16.h>

#define NN 100000
#define NE 1200000
#define NF 64
#define NH 256
#define NC 40
#define NITER 8
#define NSCAN 196                     // ceil(NN/512) scan tiles

// ---------------- scratch (device globals; no allocation) ----------------
__device__ int   g_cnt[NN];
__device__ float g_dinv[NN];
__device__ int   g_rowptr[NN + 1];
__device__ int   g_cursor[NN];
__device__ unsigned long long g_tile_state[NSCAN];  // (status<<32)|sum; 1=agg,2=prefix
__device__ int   g_tile_counter;
__device__ __align__(16) int2    g_csr[NE];         // {col*32, w as half2 bits}
// h0..h8 in fp16: (9 * 100000 * 32) half2 = 115 MB. Row = 32 half2 = 128 B.
__device__ __align__(16) __half2 g_hh[(NITER + 1) * (size_t)NN * (NF / 2)];

__device__ __forceinline__ int clampN(int v) {
    return min(max(v, 0), NN - 1);
}

// ---------------- L1: histogram (+ reset scan state for this run) ----------
__global__ void k_hist(const int* __restrict__ ei) {
    int e = blockIdx.x * blockDim.x + threadIdx.x;
    if (e < NE) atomicAdd(&g_cnt[clampN(ei[e])], 1);
    if (e < NSCAN) g_tile_state[e] = 0ULL;
    if (e == NSCAN) g_tile_counter = 0;
}

// ---------------- L2: decoupled-lookback scan + dinv + h0 init -------------
__global__ void __launch_bounds__(512) k_scan_init(const float* __restrict__ x) {
    if (blockIdx.x < NSCAN) {
        __shared__ int s[512];
        __shared__ int stile;
        __shared__ int sprefix;
        int t = threadIdx.x;
        if (t == 0) stile = atomicAdd(&g_tile_counter, 1);
        __syncthreads();
        int tile = stile;
        int i = tile * 512 + t;
        int v = (i < NN) ? g_cnt[i] : 0;
        if (i < NN) g_dinv[i] = rsqrtf((float)(v + 1));
        s[t] = v;
        __syncthreads();
        for (int off = 1; off < 512; off <<= 1) {
            int add = (t >= off) ? s[t - off] : 0;
            __syncthreads();
            s[t] += add;
            __syncthreads();
        }
        int incl = s[t];
        int agg  = s[511];
        if (t == 0) {
            if (tile == 0) {
                atomicExch(&g_tile_state[0], (2ULL << 32) | (unsigned)agg);
                sprefix = 0;
            } else {
                atomicExch(&g_tile_state[tile], (1ULL << 32) | (unsigned)agg);
                int pre = 0;
                for (int p = tile - 1; p >= 0; ) {
                    unsigned long long st;
                    do { st = atomicAdd(&g_tile_state[p], 0ULL); } while ((st >> 32) == 0);
                    pre += (int)(unsigned)st;
                    if ((st >> 32) == 2ULL) break;
                    p--;
                }
                atomicExch(&g_tile_state[tile], (2ULL << 32) | (unsigned)(pre + agg));
                sprefix = pre;
            }
        }
        __syncthreads();
        if (i < NN) {
            int rp = sprefix + incl - v;   // exclusive
            g_rowptr[i] = rp;
            g_cursor[i] = rp;
        }
        if (tile == 0 && t == 0) g_rowptr[NN] = NE;
    } else {
        int i = (blockIdx.x - NSCAN) * 512 + threadIdx.x;   // quad of 4 floats
        if (i < NN * (NF / 4)) {
            float4 v = ((const float4*)x)[i];
            __half2 a = __floats2half2_rn(v.x * 0.5f, v.y * 0.5f);
            __half2 b = __floats2half2_rn(v.z * 0.5f, v.w * 0.5f);
            *(uint2*)&g_hh[(size_t)i * 2] =
                make_uint2(*(unsigned*)&a, *(unsigned*)&b);
        }
    }
}

// ---------------- L3: scatter (+ re-zero g_cnt for next run) ----------------
__global__ void k_scatter(const int* __restrict__ ei) {
    int e = blockIdx.x * blockDim.x + threadIdx.x;
    if (e < NE) {
        int r = clampN(ei[e]);
        int c = clampN(ei[NE + e]);
        int pos = atomicAdd(&g_cursor[r], 1);
        __half2 wh = __float2half2_rn(g_dinv[r] * g_dinv[c]);
        g_csr[pos] = make_int2(c * 32, *reinterpret_cast<int*>(&wh));
    }
    if (e < NN) g_cnt[e] = 0;
}

// ---------------- SPMM: h_{it+1} = A_norm h_it ------------------------------
// 4 rows per warp; 8-lane group per row; lane = 8 features (uint4 = 4 half2).
// Uniform trip count (max of 4 rows) -> no divergence; dummy slots have w=0.
// HFMA2 even/odd chains (<=8 adds each), folded to fp32 per 16-slot chunk.
__global__ void __launch_bounds__(256) k_spmm(int it) {
    const size_t NN32 = (size_t)NN * (NF / 2);
    const __half2* __restrict__ hin = g_hh + (size_t)it * NN32;
    __half2* __restrict__ hout      = g_hh + (size_t)(it + 1) * NN32;

    __shared__ int2 se[8][4][17];    // [warp][group][slot], padded: bcast conflict-free

    int lane = threadIdx.x & 31;
    int wid  = threadIdx.x >> 5;
    int g    = lane >> 3;            // group 0..3
    int li   = lane & 7;             // lane in group

    int row = (blockIdx.x * 8 + wid) * 4 + g;   // NN divisible by 32

    int start = g_rowptr[row];
    int end   = g_rowptr[row + 1];
    int len   = end - start;
    float dr  = g_dinv[row];
    float dw  = dr * dr;

    // diagonal term in fp32: features li*8 .. li*8+7
    uint4 own = __ldg((const uint4*)(hin + (size_t)row * 32 + li * 4));
    float2 f0 = __half22float2(*(__half2*)&own.x);
    float2 f1 = __half22float2(*(__half2*)&own.y);
    float2 f2 = __half22float2(*(__half2*)&own.z);
    float2 f3 = __half22float2(*(__half2*)&own.w);
    float accf[8];
    accf[0] = dw * f0.x; accf[1] = dw * f0.y;
    accf[2] = dw * f1.x; accf[3] = dw * f1.y;
    accf[4] = dw * f2.x; accf[5] = dw * f2.y;
    accf[6] = dw * f3.x; accf[7] = dw * f3.y;

    // uniform loop bound over the 4 groups (xor 8 swaps 0<->1,2<->3; xor 16 pairs)
    int m1   = max(len, __shfl_xor_sync(0xffffffffu, len, 8));
    int mlen = max(m1,  __shfl_xor_sync(0xffffffffu, m1, 16));

    const __half2 z2 = __float2half2_rn(0.f);

    for (int b = 0; b < mlen; b += 16) {
        int idx0 = start + b + li;
        int idx1 = idx0 + 8;
        int2 e0 = (idx0 < end) ? g_csr[idx0] : make_int2(0, 0);
        int2 e1 = (idx1 < end) ? g_csr[idx1] : make_int2(0, 0);
        se[wid][g][li]     = e0;
        se[wid][g][li + 8] = e1;
        __syncwarp();

        int jm = min(16, mlen - b);
        __half2 a0 = z2, a1 = z2, a2 = z2, a3 = z2;   // even slots
        __half2 c0 = z2, c1 = z2, c2 = z2, c3 = z2;   // odd slots
#pragma unroll 4
        for (int j = 0; j < jm; j++) {
            int2    ej = se[wid][g][j];
            __half2 wj = *reinterpret_cast<__half2*>(&ej.y);
            uint4   t  = __ldg((const uint4*)(hin + ej.x + li * 4));
            __half2 t0 = *(__half2*)&t.x, t1 = *(__half2*)&t.y;
            __half2 t2 = *(__half2*)&t.z, t3 = *(__half2*)&t.w;
            if (j & 1) {
                c0 = __hfma2(wj, t0, c0); c1 = __hfma2(wj, t1, c1);
                c2 = __hfma2(wj, t2, c2); c3 = __hfma2(wj, t3, c3);
            } else {
                a0 = __hfma2(wj, t0, a0); a1 = __hfma2(wj, t1, a1);
                a2 = __hfma2(wj, t2, a2); a3 = __hfma2(wj, t3, a3);
            }
        }
        __syncwarp();

        float2 s0 = __half22float2(__hadd2(a0, c0));
        float2 s1 = __half22float2(__hadd2(a1, c1));
        float2 s2 = __half22float2(__hadd2(a2, c2));
        float2 s3 = __half22float2(__hadd2(a3, c3));
        accf[0] += s0.x; accf[1] += s0.y;
        accf[2] += s1.x; accf[3] += s1.y;
        accf[4] += s2.x; accf[5] += s2.y;
        accf[6] += s3.x; accf[7] += s3.y;
    }

    __half2 r0 = __floats2half2_rn(accf[0], accf[1]);
    __half2 r1 = __floats2half2_rn(accf[2], accf[3]);
    __half2 r2 = __floats2half2_rn(accf[4], accf[5]);
    __half2 r3 = __floats2half2_rn(accf[6], accf[7]);
    uint4 o;
    o.x = *(unsigned*)&r0; o.y = *(unsigned*)&r1;
    o.z = *(unsigned*)&r2; o.w = *(unsigned*)&r3;
    *(uint4*)(hout + (size_t)row * 32 + li * 4) = o;
}

// ---------------- fused MLP: out = relu((avg(h)) @ W1 + b1) @ W2 + b2 ------
__global__ void __launch_bounds__(256) k_mlp(const float* __restrict__ W1,
                                             const float* __restrict__ b1,
                                             const float* __restrict__ W2,
                                             const float* __restrict__ b2,
                                             float* __restrict__ out) {
    __shared__ __align__(16) float As[32 * 68];    // 8.7 KB  (padded stride 68)
    __shared__ __align__(16) float W1c[64 * 64];   // 16 KB
    __shared__ __align__(16) float Hs[32 * 68];    // 8.7 KB
    __shared__ __align__(16) float W2cT[40 * 68];  // 10.9 KB (transposed, padded)
    __shared__ float sb1[64];

    int tid = threadIdx.x;
    int rb  = blockIdx.x * 32;        // NN divisible by 32

    const float inv = 1.0f / (NITER + 1);
    const size_t NN32 = (size_t)NN * (NF / 2);
    for (int l = tid; l < 32 * 16; l += 256) {   // quads of 4 feats
        int rr = l >> 4, q = l & 15;
        float4 s = make_float4(0.f, 0.f, 0.f, 0.f);
#pragma unroll
        for (int b = 0; b <= NITER; b++) {
            const uint2* hb = (const uint2*)(g_hh + (size_t)b * NN32);
            uint2 v = __ldg(&hb[(size_t)(rb + rr) * 16 + q]);
            float2 f0 = __half22float2(*(__half2*)&v.x);
            float2 f1 = __half22float2(*(__half2*)&v.y);
            s.x += f0.x; s.y += f0.y; s.z += f1.x; s.w += f1.y;
        }
        s.x *= inv; s.y *= inv; s.z *= inv; s.w *= inv;
        *(float4*)&As[rr * 68 + q * 4] = s;
    }

    int tx  = tid & 15, ty = tid >> 4;   // hid-compute mapping: 2 rows x 4 cols
    int row = tid >> 3, cg = tid & 7;    // gemm2 mapping: 1 row x 5 cols
    float acc5[5] = {0.f, 0.f, 0.f, 0.f, 0.f};

    for (int c = 0; c < 4; c++) {
        __syncthreads();
        for (int l = tid; l < 64 * 16; l += 256) {
            int kk = l >> 4, j4 = l & 15;
            *(float4*)&W1c[kk * 64 + j4 * 4] =
                __ldg((const float4*)&W1[kk * NH + c * 64 + j4 * 4]);
        }
        for (int l = tid; l < 64 * 40; l += 256) {
            int kk = l / 40, cc = l - kk * 40;
            W2cT[cc * 68 + kk] = __ldg(&W2[(c * 64 + kk) * NC + cc]);
        }
        if (tid < 64) sb1[tid] = __ldg(&b1[c * 64 + tid]);
        __syncthreads();

        float4 hh0 = make_float4(0.f, 0.f, 0.f, 0.f);
        float4 hh1 = make_float4(0.f, 0.f, 0.f, 0.f);
#pragma unroll
        for (int k = 0; k < 64; k++) {
            float4 w = *(const float4*)&W1c[k * 64 + tx * 4];
            float a0 = As[(ty * 2 + 0) * 68 + k];
            float a1 = As[(ty * 2 + 1) * 68 + k];
            hh0.x += a0 * w.x; hh0.y += a0 * w.y; hh0.z += a0 * w.z; hh0.w += a0 * w.w;
            hh1.x += a1 * w.x; hh1.y += a1 * w.y; hh1.z += a1 * w.z; hh1.w += a1 * w.w;
        }
        float bx = sb1[tx * 4], by = sb1[tx * 4 + 1],
              bz = sb1[tx * 4 + 2], bw = sb1[tx * 4 + 3];
        float4 o0, o1;
        o0.x = fmaxf(hh0.x + bx, 0.f); o0.y = fmaxf(hh0.y + by, 0.f);
        o0.z = fmaxf(hh0.z + bz, 0.f); o0.w = fmaxf(hh0.w + bw, 0.f);
        o1.x = fmaxf(hh1.x + bx, 0.f); o1.y = fmaxf(hh1.y + by, 0.f);
        o1.z = fmaxf(hh1.z + bz, 0.f); o1.w = fmaxf(hh1.w + bw, 0.f);
        *(float4*)&Hs[(ty * 2 + 0) * 68 + tx * 4] = o0;
        *(float4*)&Hs[(ty * 2 + 1) * 68 + tx * 4] = o1;
        __syncthreads();

#pragma unroll
        for (int k4 = 0; k4 < 16; k4++) {
            float4 h = *(const float4*)&Hs[row * 68 + k4 * 4];
#pragma unroll
            for (int j = 0; j < 5; j++) {
                float4 w = *(const float4*)&W2cT[(cg * 5 + j) * 68 + k4 * 4];
                acc5[j] += h.x * w.x + h.y * w.y + h.z * w.z + h.w * w.w;
            }
        }
    }

#pragma unroll
    for (int j = 0; j < 5; j++)
        out[(size_t)(rb + row) * NC + cg * 5 + j] = acc5[j] + __ldg(&b2[cg * 5 + j]);
}

// ---------------- launch ----------------
extern "C" void kernel_launch(void* const* d_in, const int* in_sizes, int n_in,
                              void* d_out, int out_size) {
    const float* x   = (const float*)d_in[0];
    const int*   ei  = (const int*)d_in[1];   // int32 (JAX demotes int64)
    const float* W1  = (const float*)d_in[2];
    const float* b1  = (const float*)d_in[3];
    const float* W2  = (const float*)d_in[4];
    const float* b2  = (const float*)d_in[5];
    float*       out = (float*)d_out;

    int init_blocks = (NN * (NF / 4) + 511) / 512;   // 3125

    k_hist<<<(NE + 255) / 256, 256>>>(ei);                     // launch 1
    k_scan_init<<<NSCAN + init_blocks, 512>>>(x);              // launch 2
    k_scatter<<<(NE + 255) / 256, 256>>>(ei);                  // launch 3

    for (int it = 0; it < NITER; it++)                         // launches 4..11
        k_spmm<<<NN / 32, 256>>>(it);

    k_mlp<<<NN / 32, 256>>>(W1, b1, W2, b2, out);              // launch 12
}

// round 11
// speedup vs baseline: 1.1673x; 1.0047x over previous
#include <cuda_runtime.h>
#include <cuda_fp16.h>

#define NN 100000
#define NE 1200000
#define NF 64
#define NH 256
#define NC 40
#define NITER 8
#define NSCAN 196                     // ceil(NN/512) scan tiles
#define NDEG 1024                     // degree bins for counting sort

// ---------------- scratch (device globals; no allocation) ----------------
__device__ int   g_cnt[NN];
__device__ float g_dinv[NN];
__device__ int   g_rowptr[NN + 1];
__device__ int   g_cursor[NN];
__device__ int   g_perm[NN];          // rows in ascending-degree order
__device__ int   g_degcnt[NDEG];
__device__ int   g_degoff[NDEG];
__device__ unsigned long long g_tile_state[NSCAN];  // (status<<32)|sum; 1=agg,2=prefix
__device__ int   g_tile_counter;
__device__ __align__(16) int2    g_csr[NE];         // {col*32, w as half2 bits}
// h0..h8 in fp16: (9 * 100000 * 32) half2 = 115 MB. Row = 32 half2 = 128 B.
__device__ __align__(16) __half2 g_hh[(NITER + 1) * (size_t)NN * (NF / 2)];

__device__ __forceinline__ int clampN(int v) {
    return min(max(v, 0), NN - 1);
}

// ---------------- L1: histogram (+ reset per-run state) ----------
// Invariant: g_cnt zero on entry (zeroed at load; re-zeroed by k_scatter).
__global__ void k_hist(const int* __restrict__ ei) {
    int e = blockIdx.x * blockDim.x + threadIdx.x;
    if (e < NE) atomicAdd(&g_cnt[clampN(ei[e])], 1);
    if (e < NSCAN) g_tile_state[e] = 0ULL;
    if (e < NDEG)  g_degcnt[e] = 0;
    if (e == NSCAN) g_tile_counter = 0;
}

// ---------------- L2: decoupled-lookback scan + dinv + deg-hist + h0 init --
__global__ void __launch_bounds__(512) k_scan_init(const float* __restrict__ x) {
    if (blockIdx.x < NSCAN) {
        __shared__ int s[512];
        __shared__ int stile;
        __shared__ int sprefix;
        int t = threadIdx.x;
        if (t == 0) stile = atomicAdd(&g_tile_counter, 1);
        __syncthreads();
        int tile = stile;
        int i = tile * 512 + t;
        int v = (i < NN) ? g_cnt[i] : 0;
        if (i < NN) {
            g_dinv[i] = rsqrtf((float)(v + 1));
            atomicAdd(&g_degcnt[min(v, NDEG - 1)], 1);
        }
        s[t] = v;
        __syncthreads();
        for (int off = 1; off < 512; off <<= 1) {
            int add = (t >= off) ? s[t - off] : 0;
            __syncthreads();
            s[t] += add;
            __syncthreads();
        }
        int incl = s[t];
        int agg  = s[511];
        if (t == 0) {
            if (tile == 0) {
                atomicExch(&g_tile_state[0], (2ULL << 32) | (unsigned)agg);
                sprefix = 0;
            } else {
                atomicExch(&g_tile_state[tile], (1ULL << 32) | (unsigned)agg);
                int pre = 0;
                for (int p = tile - 1; p >= 0; ) {
                    unsigned long long st;
                    do { st = atomicAdd(&g_tile_state[p], 0ULL); } while ((st >> 32) == 0);
                    pre += (int)(unsigned)st;
                    if ((st >> 32) == 2ULL) break;
                    p--;
                }
                atomicExch(&g_tile_state[tile], (2ULL << 32) | (unsigned)(pre + agg));
                sprefix = pre;
            }
        }
        __syncthreads();
        if (i < NN) {
            int rp = sprefix + incl - v;   // exclusive
            g_rowptr[i] = rp;
            g_cursor[i] = rp;
        }
        if (tile == 0 && t == 0) g_rowptr[NN] = NE;
    } else {
        int i = (blockIdx.x - NSCAN) * 512 + threadIdx.x;   // quad of 4 floats
        if (i < NN * (NF / 4)) {
            float4 v = ((const float4*)x)[i];
            __half2 a = __floats2half2_rn(v.x * 0.5f, v.y * 0.5f);
            __half2 b = __floats2half2_rn(v.z * 0.5f, v.w * 0.5f);
            *(uint2*)&g_hh[(size_t)i * 2] =
                make_uint2(*(unsigned*)&a, *(unsigned*)&b);
        }
    }
}

// ---------------- L2b: exclusive scan of 1024 degree bins (1 block) --------
__global__ void __launch_bounds__(1024) k_degscan() {
    __shared__ int s[NDEG];
    int t = threadIdx.x;
    int v = g_degcnt[t];
    s[t] = v;
    __syncthreads();
    for (int off = 1; off < NDEG; off <<= 1) {
        int add = (t >= off) ? s[t - off] : 0;
        __syncthreads();
        s[t] += add;
        __syncthreads();
    }
    g_degoff[t] = s[t] - v;   // exclusive
}

// ---------------- L3: scatter edges + perm scatter + re-zero g_cnt ---------
__global__ void k_scatter(const int* __restrict__ ei) {
    int e = blockIdx.x * blockDim.x + threadIdx.x;
    if (e < NE) {
        int r = clampN(ei[e]);
        int c = clampN(ei[NE + e]);
        int pos = atomicAdd(&g_cursor[r], 1);
        __half2 wh = __float2half2_rn(g_dinv[r] * g_dinv[c]);
        g_csr[pos] = make_int2(c * 32, *reinterpret_cast<int*>(&wh));
    }
    if (e < NN) {
        int d = g_cnt[e];
        int p = atomicAdd(&g_degoff[min(d, NDEG - 1)], 1);
        g_perm[p] = e;
        g_cnt[e] = 0;
    }
}

// ---------------- SPMM: h_{it+1} = A_norm h_it ------------------------------
// Rows processed in degree-sorted order (g_perm): the 4 rows of a warp have
// ~equal degree -> minimal dummy work, balanced warps. 8-lane group per row;
// lane = 8 features (uint4). Inner loop is a FIXED 16 iterations (compile-time
// trip) so ptxas front-batches the 16 gathers -> high MLP; dummy slots w=0.
__global__ void __launch_bounds__(256) k_spmm(int it) {
    const size_t NN32 = (size_t)NN * (NF / 2);
    const __half2* __restrict__ hin = g_hh + (size_t)it * NN32;
    __half2* __restrict__ hout      = g_hh + (size_t)(it + 1) * NN32;

    __shared__ int2 se[8][4][17];    // [warp][group][slot], padded

    int lane = threadIdx.x & 31;
    int wid  = threadIdx.x >> 5;
    int g    = lane >> 3;            // group 0..3
    int li   = lane & 7;             // lane in group

    int row = g_perm[(blockIdx.x * 8 + wid) * 4 + g];   // NN divisible by 32

    int start = g_rowptr[row];
    int end   = g_rowptr[row + 1];
    int len   = end - start;
    float dr  = g_dinv[row];
    float dw  = dr * dr;

    // diagonal term in fp32: features li*8 .. li*8+7
    uint4 own = __ldg((const uint4*)(hin + (size_t)row * 32 + li * 4));
    float2 f0 = __half22float2(*(__half2*)&own.x);
    float2 f1 = __half22float2(*(__half2*)&own.y);
    float2 f2 = __half22float2(*(__half2*)&own.z);
    float2 f3 = __half22float2(*(__half2*)&own.w);
    float accf[8];
    accf[0] = dw * f0.x; accf[1] = dw * f0.y;
    accf[2] = dw * f1.x; accf[3] = dw * f1.y;
    accf[4] = dw * f2.x; accf[5] = dw * f2.y;
    accf[6] = dw * f3.x; accf[7] = dw * f3.y;

    // uniform loop bound over the 4 groups (sorted rows -> nearly equal)
    int m1   = max(len, __shfl_xor_sync(0xffffffffu, len, 8));
    int mlen = max(m1,  __shfl_xor_sync(0xffffffffu, m1, 16));

    const __half2 z2 = __float2half2_rn(0.f);

    for (int b = 0; b < mlen; b += 16) {
        int idx0 = start + b + li;
        int idx1 = idx0 + 8;
        int2 e0 = (idx0 < end) ? g_csr[idx0] : make_int2(0, 0);
        int2 e1 = (idx1 < end) ? g_csr[idx1] : make_int2(0, 0);
        se[wid][g][li]     = e0;
        se[wid][g][li + 8] = e1;
        __syncwarp();

        __half2 a0 = z2, a1 = z2, a2 = z2, a3 = z2;   // even slots
        __half2 c0 = z2, c1 = z2, c2 = z2, c3 = z2;   // odd slots
#pragma unroll
        for (int j = 0; j < 16; j++) {                // fixed trip: batched LDGs
            int2    ej = se[wid][g][j];
            __half2 wj = *reinterpret_cast<__half2*>(&ej.y);
            uint4   t  = __ldg((const uint4*)(hin + ej.x + li * 4));
            __half2 t0 = *(__half2*)&t.x, t1 = *(__half2*)&t.y;
            __half2 t2 = *(__half2*)&t.z, t3 = *(__half2*)&t.w;
            if (j & 1) {
                c0 = __hfma2(wj, t0, c0); c1 = __hfma2(wj, t1, c1);
                c2 = __hfma2(wj, t2, c2); c3 = __hfma2(wj, t3, c3);
            } else {
                a0 = __hfma2(wj, t0, a0); a1 = __hfma2(wj, t1, a1);
                a2 = __hfma2(wj, t2, a2); a3 = __hfma2(wj, t3, a3);
            }
        }
        __syncwarp();

        float2 s0 = __half22float2(__hadd2(a0, c0));
        float2 s1 = __half22float2(__hadd2(a1, c1));
        float2 s2 = __half22float2(__hadd2(a2, c2));
        float2 s3 = __half22float2(__hadd2(a3, c3));
        accf[0] += s0.x; accf[1] += s0.y;
        accf[2] += s1.x; accf[3] += s1.y;
        accf[4] += s2.x; accf[5] += s2.y;
        accf[6] += s3.x; accf[7] += s3.y;
    }

    __half2 r0 = __floats2half2_rn(accf[0], accf[1]);
    __half2 r1 = __floats2half2_rn(accf[2], accf[3]);
    __half2 r2 = __floats2half2_rn(accf[4], accf[5]);
    __half2 r3 = __floats2half2_rn(accf[6], accf[7]);
    uint4 o;
    o.x = *(unsigned*)&r0; o.y = *(unsigned*)&r1;
    o.z = *(unsigned*)&r2; o.w = *(unsigned*)&r3;
    *(uint4*)(hout + (size_t)row * 32 + li * 4) = o;
}

// ---------------- fused MLP: out = relu((avg(h)) @ W1 + b1) @ W2 + b2 ------
__global__ void __launch_bounds__(256) k_mlp(const float* __restrict__ W1,
                                             const float* __restrict__ b1,
                                             const float* __restrict__ W2,
                                             const float* __restrict__ b2,
                                             float* __restrict__ out) {
    __shared__ __align__(16) float As[32 * 68];    // 8.7 KB  (padded stride 68)
    __shared__ __align__(16) float W1c[64 * 64];   // 16 KB
    __shared__ __align__(16) float Hs[32 * 68];    // 8.7 KB
    __shared__ __align__(16) float W2cT[40 * 68];  // 10.9 KB (transposed, padded)
    __shared__ float sb1[64];

    int tid = threadIdx.x;
    int rb  = blockIdx.x * 32;        // NN divisible by 32

    const float inv = 1.0f / (NITER + 1);
    const size_t NN32 = (size_t)NN * (NF / 2);
    for (int l = tid; l < 32 * 16; l += 256) {   // quads of 4 feats
        int rr = l >> 4, q = l & 15;
        float4 s = make_float4(0.f, 0.f, 0.f, 0.f);
#pragma unroll
        for (int b = 0; b <= NITER; b++) {
            const uint2* hb = (const uint2*)(g_hh + (size_t)b * NN32);
            uint2 v = __ldg(&hb[(size_t)(rb + rr) * 16 + q]);
            float2 f0 = __half22float2(*(__half2*)&v.x);
            float2 f1 = __half22float2(*(__half2*)&v.y);
            s.x += f0.x; s.y += f0.y; s.z += f1.x; s.w += f1.y;
        }
        s.x *= inv; s.y *= inv; s.z *= inv; s.w *= inv;
        *(float4*)&As[rr * 68 + q * 4] = s;
    }

    int tx  = tid & 15, ty = tid >> 4;   // hid-compute mapping: 2 rows x 4 cols
    int row = tid >> 3, cg = tid & 7;    // gemm2 mapping: 1 row x 5 cols
    float acc5[5] = {0.f, 0.f, 0.f, 0.f, 0.f};

    for (int c = 0; c < 4; c++) {
        __syncthreads();
        for (int l = tid; l < 64 * 16; l += 256) {
            int kk = l >> 4, j4 = l & 15;
            *(float4*)&W1c[kk * 64 + j4 * 4] =
                __ldg((const float4*)&W1[kk * NH + c * 64 + j4 * 4]);
        }
        for (int l = tid; l < 64 * 40; l += 256) {
            int kk = l / 40, cc = l - kk * 40;
            W2cT[cc * 68 + kk] = __ldg(&W2[(c * 64 + kk) * NC + cc]);
        }
        if (tid < 64) sb1[tid] = __ldg(&b1[c * 64 + tid]);
        __syncthreads();

        float4 hh0 = make_float4(0.f, 0.f, 0.f, 0.f);
        float4 hh1 = make_float4(0.f, 0.f, 0.f, 0.f);
#pragma unroll
        for (int k = 0; k < 64; k++) {
            float4 w = *(const float4*)&W1c[k * 64 + tx * 4];
            float a0 = As[(ty * 2 + 0) * 68 + k];
            float a1 = As[(ty * 2 + 1) * 68 + k];
            hh0.x += a0 * w.x; hh0.y += a0 * w.y; hh0.z += a0 * w.z; hh0.w += a0 * w.w;
            hh1.x += a1 * w.x; hh1.y += a1 * w.y; hh1.z += a1 * w.z; hh1.w += a1 * w.w;
        }
        float bx = sb1[tx * 4], by = sb1[tx * 4 + 1],
              bz = sb1[tx * 4 + 2], bw = sb1[tx * 4 + 3];
        float4 o0, o1;
        o0.x = fmaxf(hh0.x + bx, 0.f); o0.y = fmaxf(hh0.y + by, 0.f);
        o0.z = fmaxf(hh0.z + bz, 0.f); o0.w = fmaxf(hh0.w + bw, 0.f);
        o1.x = fmaxf(hh1.x + bx, 0.f); o1.y = fmaxf(hh1.y + by, 0.f);
        o1.z = fmaxf(hh1.z + bz, 0.f); o1.w = fmaxf(hh1.w + bw, 0.f);
        *(float4*)&Hs[(ty * 2 + 0) * 68 + tx * 4] = o0;
        *(float4*)&Hs[(ty * 2 + 1) * 68 + tx * 4] = o1;
        __syncthreads();

#pragma unroll
        for (int k4 = 0; k4 < 16; k4++) {
            float4 h = *(const float4*)&Hs[row * 68 + k4 * 4];
#pragma unroll
            for (int j = 0; j < 5; j++) {
                float4 w = *(const float4*)&W2cT[(cg * 5 + j) * 68 + k4 * 4];
                acc5[j] += h.x * w.x + h.y * w.y + h.z * w.z + h.w * w.w;
            }
        }
    }

#pragma unroll
    for (int j = 0; j < 5; j++)
        out[(size_t)(rb + row) * NC + cg * 5 + j] = acc5[j] + __ldg(&b2[cg * 5 + j]);
}

// ---------------- launch ----------------
extern "C" void kernel_launch(void* const* d_in, const int* in_sizes, int n_in,
                              void* d_out, int out_size) {
    const float* x   = (const float*)d_in[0];
    const int*   ei  = (const int*)d_in[1];   // int32 (JAX demotes int64)
    const float* W1  = (const float*)d_in[2];
    const float* b1  = (const float*)d_in[3];
    const float* W2  = (const float*)d_in[4];
    const float* b2  = (const float*)d_in[5];
    float*       out = (float*)d_out;

    int init_blocks = (NN * (NF / 4) + 511) / 512;   // 3125

    k_hist<<<(NE + 255) / 256, 256>>>(ei);                     // launch 1
    k_scan_init<<<NSCAN + init_blocks, 512>>>(x);              // launch 2
    k_degscan<<<1, NDEG>>>();                                  // launch 3
    k_scatter<<<(NE + 255) / 256, 256>>>(ei);                  // launch 4

    for (int it = 0; it < NITER; it++)                         // launches 5..12
        k_spmm<<<NN / 32, 256>>>(it);

    k_mlp<<<NN / 32, 256>>>(W1, b1, W2, b2, out);              // launch 13
}

// round 12
// speedup vs baseline: 1.7886x; 1.5322x over previous
#include <cuda_runtime.h>
#include <cuda_fp16.h>
#include <mma.h>

using namespace nvcuda;

#define NN 100000
#define NE 1200000
#define NF 64
#define NH 256
#define NC 40
#define NITER 8
#define NSCAN 196                     // ceil(NN/512) scan tiles
#define NDEG 1024                     // degree bins for counting sort

// ---------------- scratch (device globals; no allocation) ----------------
__device__ int   g_cnt[NN];
__device__ float g_dinv[NN];
__device__ int   g_rowptr[NN + 1];
__device__ int   g_cursor[NN];
__device__ int   g_perm[NN];          // rows in ascending-degree order
__device__ int   g_degcnt[NDEG];
__device__ int   g_degoff[NDEG];
__device__ unsigned long long g_tile_state[NSCAN];  // (status<<32)|sum; 1=agg,2=prefix
__device__ int   g_tile_counter;
__device__ __align__(16) int2    g_csr[NE];         // {col*32, w as half2 bits}
// h0..h8 in fp16: (9 * 100000 * 32) half2 = 115 MB. Row = 32 half2 = 128 B.
__device__ __align__(16) __half2 g_hh[(NITER + 1) * (size_t)NN * (NF / 2)];

__device__ __forceinline__ int clampN(int v) {
    return min(max(v, 0), NN - 1);
}

// ---------------- L1: histogram (+ reset per-run state) ----------
__global__ void k_hist(const int* __restrict__ ei) {
    int e = blockIdx.x * blockDim.x + threadIdx.x;
    if (e < NE) atomicAdd(&g_cnt[clampN(ei[e])], 1);
    if (e < NSCAN) g_tile_state[e] = 0ULL;
    if (e < NDEG)  g_degcnt[e] = 0;
    if (e == NSCAN) g_tile_counter = 0;
}

// ---------------- L2: decoupled-lookback scan + dinv + deg-hist + h0 init --
__global__ void __launch_bounds__(512) k_scan_init(const float* __restrict__ x) {
    if (blockIdx.x < NSCAN) {
        __shared__ int s[512];
        __shared__ int stile;
        __shared__ int sprefix;
        int t = threadIdx.x;
        if (t == 0) stile = atomicAdd(&g_tile_counter, 1);
        __syncthreads();
        int tile = stile;
        int i = tile * 512 + t;
        int v = (i < NN) ? g_cnt[i] : 0;
        if (i < NN) {
            g_dinv[i] = rsqrtf((float)(v + 1));
            atomicAdd(&g_degcnt[min(v, NDEG - 1)], 1);
        }
        s[t] = v;
        __syncthreads();
        for (int off = 1; off < 512; off <<= 1) {
            int add = (t >= off) ? s[t - off] : 0;
            __syncthreads();
            s[t] += add;
            __syncthreads();
        }
        int incl = s[t];
        int agg  = s[511];
        if (t == 0) {
            if (tile == 0) {
                atomicExch(&g_tile_state[0], (2ULL << 32) | (unsigned)agg);
                sprefix = 0;
            } else {
                atomicExch(&g_tile_state[tile], (1ULL << 32) | (unsigned)agg);
                int pre = 0;
                for (int p = tile - 1; p >= 0; ) {
                    unsigned long long st;
                    do { st = atomicAdd(&g_tile_state[p], 0ULL); } while ((st >> 32) == 0);
                    pre += (int)(unsigned)st;
                    if ((st >> 32) == 2ULL) break;
                    p--;
                }
                atomicExch(&g_tile_state[tile], (2ULL << 32) | (unsigned)(pre + agg));
                sprefix = pre;
            }
        }
        __syncthreads();
        if (i < NN) {
            int rp = sprefix + incl - v;   // exclusive
            g_rowptr[i] = rp;
            g_cursor[i] = rp;
        }
        if (tile == 0 && t == 0) g_rowptr[NN] = NE;
    } else {
        int i = (blockIdx.x - NSCAN) * 512 + threadIdx.x;   // quad of 4 floats
        if (i < NN * (NF / 4)) {
            float4 v = ((const float4*)x)[i];
            __half2 a = __floats2half2_rn(v.x * 0.5f, v.y * 0.5f);
            __half2 b = __floats2half2_rn(v.z * 0.5f, v.w * 0.5f);
            *(uint2*)&g_hh[(size_t)i * 2] =
                make_uint2(*(unsigned*)&a, *(unsigned*)&b);
        }
    }
}

// ---------------- L2b: exclusive scan of 1024 degree bins (1 block) --------
__global__ void __launch_bounds__(1024) k_degscan() {
    __shared__ int s[NDEG];
    int t = threadIdx.x;
    int v = g_degcnt[t];
    s[t] = v;
    __syncthreads();
    for (int off = 1; off < NDEG; off <<= 1) {
        int add = (t >= off) ? s[t - off] : 0;
        __syncthreads();
        s[t] += add;
        __syncthreads();
    }
    g_degoff[t] = s[t] - v;   // exclusive
}

// ---------------- L3: scatter edges + perm scatter + re-zero g_cnt ---------
__global__ void k_scatter(const int* __restrict__ ei) {
    int e = blockIdx.x * blockDim.x + threadIdx.x;
    if (e < NE) {
        int r = clampN(ei[e]);
        int c = clampN(ei[NE + e]);
        int pos = atomicAdd(&g_cursor[r], 1);
        __half2 wh = __float2half2_rn(g_dinv[r] * g_dinv[c]);
        g_csr[pos] = make_int2(c * 32, *reinterpret_cast<int*>(&wh));
    }
    if (e < NN) {
        int d = g_cnt[e];
        int p = atomicAdd(&g_degoff[min(d, NDEG - 1)], 1);
        g_perm[p] = e;
        g_cnt[e] = 0;
    }
}

// ---------------- SPMM: h_{it+1} = A_norm h_it ------------------------------
__global__ void __launch_bounds__(256) k_spmm(int it) {
    const size_t NN32 = (size_t)NN * (NF / 2);
    const __half2* __restrict__ hin = g_hh + (size_t)it * NN32;
    __half2* __restrict__ hout      = g_hh + (size_t)(it + 1) * NN32;

    __shared__ int2 se[8][4][17];    // [warp][group][slot], padded

    int lane = threadIdx.x & 31;
    int wid  = threadIdx.x >> 5;
    int g    = lane >> 3;            // group 0..3
    int li   = lane & 7;             // lane in group

    int row = g_perm[(blockIdx.x * 8 + wid) * 4 + g];   // NN divisible by 32

    int start = g_rowptr[row];
    int end   = g_rowptr[row + 1];
    int len   = end - start;
    float dr  = g_dinv[row];
    float dw  = dr * dr;

    uint4 own = __ldg((const uint4*)(hin + (size_t)row * 32 + li * 4));
    float2 f0 = __half22float2(*(__half2*)&own.x);
    float2 f1 = __half22float2(*(__half2*)&own.y);
    float2 f2 = __half22float2(*(__half2*)&own.z);
    float2 f3 = __half22float2(*(__half2*)&own.w);
    float accf[8];
    accf[0] = dw * f0.x; accf[1] = dw * f0.y;
    accf[2] = dw * f1.x; accf[3] = dw * f1.y;
    accf[4] = dw * f2.x; accf[5] = dw * f2.y;
    accf[6] = dw * f3.x; accf[7] = dw * f3.y;

    int m1   = max(len, __shfl_xor_sync(0xffffffffu, len, 8));
    int mlen = max(m1,  __shfl_xor_sync(0xffffffffu, m1, 16));

    const __half2 z2 = __float2half2_rn(0.f);

    for (int b = 0; b < mlen; b += 16) {
        int idx0 = start + b + li;
        int idx1 = idx0 + 8;
        int2 e0 = (idx0 < end) ? g_csr[idx0] : make_int2(0, 0);
        int2 e1 = (idx1 < end) ? g_csr[idx1] : make_int2(0, 0);
        se[wid][g][li]     = e0;
        se[wid][g][li + 8] = e1;
        __syncwarp();

        __half2 a0 = z2, a1 = z2, a2 = z2, a3 = z2;   // even slots
        __half2 c0 = z2, c1 = z2, c2 = z2, c3 = z2;   // odd slots
#pragma unroll
        for (int j = 0; j < 16; j++) {                // fixed trip: batched LDGs
            int2    ej = se[wid][g][j];
            __half2 wj = *reinterpret_cast<__half2*>(&ej.y);
            uint4   t  = __ldg((const uint4*)(hin + ej.x + li * 4));
            __half2 t0 = *(__half2*)&t.x, t1 = *(__half2*)&t.y;
            __half2 t2 = *(__half2*)&t.z, t3 = *(__half2*)&t.w;
            if (j & 1) {
                c0 = __hfma2(wj, t0, c0); c1 = __hfma2(wj, t1, c1);
                c2 = __hfma2(wj, t2, c2); c3 = __hfma2(wj, t3, c3);
            } else {
                a0 = __hfma2(wj, t0, a0); a1 = __hfma2(wj, t1, a1);
                a2 = __hfma2(wj, t2, a2); a3 = __hfma2(wj, t3, a3);
            }
        }
        __syncwarp();

        float2 s0 = __half22float2(__hadd2(a0, c0));
        float2 s1 = __half22float2(__hadd2(a1, c1));
        float2 s2 = __half22float2(__hadd2(a2, c2));
        float2 s3 = __half22float2(__hadd2(a3, c3));
        accf[0] += s0.x; accf[1] += s0.y;
        accf[2] += s1.x; accf[3] += s1.y;
        accf[4] += s2.x; accf[5] += s2.y;
        accf[6] += s3.x; accf[7] += s3.y;
    }

    __half2 r0 = __floats2half2_rn(accf[0], accf[1]);
    __half2 r1 = __floats2half2_rn(accf[2], accf[3]);
    __half2 r2 = __floats2half2_rn(accf[4], accf[5]);
    __half2 r3 = __floats2half2_rn(accf[6], accf[7]);
    uint4 o;
    o.x = *(unsigned*)&r0; o.y = *(unsigned*)&r1;
    o.z = *(unsigned*)&r2; o.w = *(unsigned*)&r3;
    *(uint4*)(hout + (size_t)row * 32 + li * 4) = o;
}

// ---------------- fused MLP on tensor cores (wmma m16n16k16, f32 accum) ----
// block = 32 rows, 256 threads = 8 warps. hid in 4 chunks of 64 cols.
// gemm1: 8 warps x one 16x16 hid fragment (M2 x N4 tiling), K=4 steps.
// gemm2: warps 0..5 hold persistent 16x16 out fragments (M2 x N3, N padded
// 40->48) accumulated across all 4 chunks.
#define LDA 72   // fp16 lds (mult of 8)
#define LDB 48   // W2 cols padded
__global__ void __launch_bounds__(256) k_mlp(const float* __restrict__ W1,
                                             const float* __restrict__ b1,
                                             const float* __restrict__ W2,
                                             const float* __restrict__ b2,
                                             float* __restrict__ out) {
    __shared__ __align__(16) __half AsH[32 * LDA];    // 4.6 KB
    __shared__ __align__(16) __half W1cH[64 * LDA];   // 9.2 KB
    __shared__ __align__(16) float  HsF[32 * LDA];    // 9.2 KB
    __shared__ __align__(16) __half HsH[32 * LDA];    // 4.6 KB
    __shared__ __align__(16) __half W2cH[64 * LDB];   // 6.1 KB
    __shared__ __align__(16) float  OutF[32 * LDB];   // 6.1 KB

    int tid = threadIdx.x;
    int wid = tid >> 5;
    int rb  = blockIdx.x * 32;        // NN divisible by 32

    // As = (1/9) * sum_{b=0..8} h_b  [32 x 64], fp32 accumulation -> fp16
    const float inv = 1.0f / (NITER + 1);
    const size_t NN32 = (size_t)NN * (NF / 2);
    for (int l = tid; l < 32 * 16; l += 256) {   // quads of 4 feats
        int rr = l >> 4, q = l & 15;
        float4 s = make_float4(0.f, 0.f, 0.f, 0.f);
#pragma unroll
        for (int b = 0; b <= NITER; b++) {
            const uint2* hb = (const uint2*)(g_hh + (size_t)b * NN32);
            uint2 v = __ldg(&hb[(size_t)(rb + rr) * 16 + q]);
            float2 f0 = __half22float2(*(__half2*)&v.x);
            float2 f1 = __half22float2(*(__half2*)&v.y);
            s.x += f0.x; s.y += f0.y; s.z += f1.x; s.w += f1.y;
        }
        __half2 p0 = __floats2half2_rn(s.x * inv, s.y * inv);
        __half2 p1 = __floats2half2_rn(s.z * inv, s.w * inv);
        *(uint2*)&AsH[rr * LDA + q * 4] =
            make_uint2(*(unsigned*)&p0, *(unsigned*)&p1);
    }

    wmma::fragment<wmma::accumulator, 16, 16, 16, float> ofrag;
    int omi = wid / 3, oni = wid % 3;   // warps 0..5: out tile (omi, oni)
    if (wid < 6) wmma::fill_fragment(ofrag, 0.f);

    for (int c = 0; c < 4; c++) {
        __syncthreads();   // prev chunk's W1cH/W2cH/HsH fully consumed
        // W1 chunk [64 x 64] -> fp16
        for (int l = tid; l < 64 * 64; l += 256) {
            int kk = l >> 6, j = l & 63;
            W1cH[kk * LDA + j] = __float2half(__ldg(&W1[kk * NH + c * 64 + j]));
        }
        // W2 chunk [64 x 40] -> fp16, zero-padded to 48 cols
        for (int l = tid; l < 64 * LDB; l += 256) {
            int kk = l / LDB, n = l % LDB;
            W2cH[kk * LDB + n] =
                (n < NC) ? __float2half(__ldg(&W2[(c * 64 + kk) * NC + n]))
                         : __half(0.f);
        }
        __syncthreads();

        // gemm1: hid chunk [32 x 64] = AsH[32 x 64] @ W1cH[64 x 64]
        {
            int mi = wid >> 2, ni = wid & 3;
            wmma::fragment<wmma::accumulator, 16, 16, 16, float> hfrag;
            wmma::fill_fragment(hfrag, 0.f);
#pragma unroll
            for (int k = 0; k < 4; k++) {
                wmma::fragment<wmma::matrix_a, 16, 16, 16, __half, wmma::row_major> af;
                wmma::fragment<wmma::matrix_b, 16, 16, 16, __half, wmma::row_major> bf;
                wmma::load_matrix_sync(af, &AsH[mi * 16 * LDA + k * 16], LDA);
                wmma::load_matrix_sync(bf, &W1cH[k * 16 * LDA + ni * 16], LDA);
                wmma::mma_sync(hfrag, af, bf, hfrag);
            }
            wmma::store_matrix_sync(&HsF[mi * 16 * LDA + ni * 16], hfrag, LDA,
                                    wmma::mem_row_major);
        }
        __syncthreads();

        // bias + relu + fp16
        for (int l = tid; l < 32 * 64; l += 256) {
            int r = l >> 6, j = l & 63;
            float v = HsF[r * LDA + j] + __ldg(&b1[c * 64 + j]);
            HsH[r * LDA + j] = __float2half(fmaxf(v, 0.f));
        }
        __syncthreads();

        // gemm2 partial: OutF += HsH[32 x 64] @ W2cH[64 x 48]
        if (wid < 6) {
#pragma unroll
            for (int k = 0; k < 4; k++) {
                wmma::fragment<wmma::matrix_a, 16, 16, 16, __half, wmma::row_major> af;
                wmma::fragment<wmma::matrix_b, 16, 16, 16, __half, wmma::row_major> bf;
                wmma::load_matrix_sync(af, &HsH[omi * 16 * LDA + k * 16], LDA);
                wmma::load_matrix_sync(bf, &W2cH[k * 16 * LDB + oni * 16], LDB);
                wmma::mma_sync(ofrag, af, bf, ofrag);
            }
        }
    }

    __syncthreads();
    if (wid < 6)
        wmma::store_matrix_sync(&OutF[omi * 16 * LDB + oni * 16], ofrag, LDB,
                                wmma::mem_row_major);
    __syncthreads();

    for (int l = tid; l < 32 * NC; l += 256) {
        int r = l / NC, n = l - r * NC;
        out[(size_t)(rb + r) * NC + n] = OutF[r * LDB + n] + __ldg(&b2[n]);
    }
}

// ---------------- launch ----------------
extern "C" void kernel_launch(void* const* d_in, const int* in_sizes, int n_in,
                              void* d_out, int out_size) {
    const float* x   = (const float*)d_in[0];
    const int*   ei  = (const int*)d_in[1];   // int32 (JAX demotes int64)
    const float* W1  = (const float*)d_in[2];
    const float* b1  = (const float*)d_in[3];
    const float* W2  = (const float*)d_in[4];
    const float* b2  = (const float*)d_in[5];
    float*       out = (float*)d_out;

    int init_blocks = (NN * (NF / 4) + 511) / 512;   // 3125

    k_hist<<<(NE + 255) / 256, 256>>>(ei);                     // launch 1
    k_scan_init<<<NSCAN + init_blocks, 512>>>(x);              // launch 2
    k_degscan<<<1, NDEG>>>();                                  // launch 3
    k_scatter<<<(NE + 255) / 256, 256>>>(ei);                  // launch 4

    for (int it = 0; it < NITER; it++)                         // launches 5..12
        k_spmm<<<NN / 32, 256>>>(it);

    k_mlp<<<NN / 32, 256>>>(W1, b1, W2, b2, out);              // launch 13
}

// round 13
// speedup vs baseline: 1.8086x; 1.0112x over previous
#include <cuda_runtime.h>
#include <cuda_fp16.h>
#include <mma.h>

using namespace nvcuda;

#define NN 100000
#define NE 1200000
#define NCSR (NE + NN)                // edges + self-loops
#define NF 64
#define NH 256
#define NC 40
#define NITER 8
#define NSCAN 196                     // ceil(NN/512) scan tiles
#define NDEG 1024                     // degree bins for counting sort

// ---------------- scratch (device globals; no allocation) ----------------
__device__ int   g_cnt[NN];
__device__ float g_dinv[NN];
__device__ int   g_rowptr[NN + 1];
__device__ int   g_cursor[NN];
__device__ int   g_degcnt[NDEG];
__device__ int   g_degoff[NDEG];
__device__ unsigned long long g_tile_state[NSCAN];  // (status<<32)|sum; 1=agg,2=prefix
__device__ int   g_tile_counter;
__device__ __align__(16) int4    g_task[NN];        // {start, len, row*32, 0} sorted by degree
__device__ __align__(16) int2    g_csr[NCSR];       // {col*32, w as half2 bits}
// h0..h8 in fp16: (9 * 100000 * 32) half2 = 115 MB. Row = 32 half2 = 128 B.
__device__ __align__(16) __half2 g_hh[(NITER + 1) * (size_t)NN * (NF / 2)];

__device__ __forceinline__ int clampN(int v) {
    return min(max(v, 0), NN - 1);
}

// ---------------- L1: histogram (+ reset per-run state) ----------
// Invariant: g_cnt zero on entry (zeroed at load; re-zeroed by k_scatter).
__global__ void k_hist(const int* __restrict__ ei) {
    int e = blockIdx.x * blockDim.x + threadIdx.x;
    if (e < NE) atomicAdd(&g_cnt[clampN(ei[e])], 1);
    if (e < NSCAN) g_tile_state[e] = 0ULL;
    if (e < NDEG)  g_degcnt[e] = 0;
    if (e == NSCAN) g_tile_counter = 0;
}

// ---------------- L2: decoupled-lookback scan + dinv + deg-hist + h0 init --
// rowptr scans (deg+1): self-loops are CSR entries.
__global__ void __launch_bounds__(512) k_scan_init(const float* __restrict__ x) {
    if (blockIdx.x < NSCAN) {
        __shared__ int s[512];
        __shared__ int stile;
        __shared__ int sprefix;
        int t = threadIdx.x;
        if (t == 0) stile = atomicAdd(&g_tile_counter, 1);
        __syncthreads();
        int tile = stile;
        int i = tile * 512 + t;
        int deg = (i < NN) ? g_cnt[i] : 0;
        int v   = (i < NN) ? deg + 1 : 0;     // +1 self-loop slot
        if (i < NN) {
            g_dinv[i] = rsqrtf((float)(deg + 1));
            atomicAdd(&g_degcnt[min(deg, NDEG - 1)], 1);
        }
        s[t] = v;
        __syncthreads();
        for (int off = 1; off < 512; off <<= 1) {
            int add = (t >= off) ? s[t - off] : 0;
            __syncthreads();
            s[t] += add;
            __syncthreads();
        }
        int incl = s[t];
        int agg  = s[511];
        if (t == 0) {
            if (tile == 0) {
                atomicExch(&g_tile_state[0], (2ULL << 32) | (unsigned)agg);
                sprefix = 0;
            } else {
                atomicExch(&g_tile_state[tile], (1ULL << 32) | (unsigned)agg);
                int pre = 0;
                for (int p = tile - 1; p >= 0; ) {
                    unsigned long long st;
                    do { st = atomicAdd(&g_tile_state[p], 0ULL); } while ((st >> 32) == 0);
                    pre += (int)(unsigned)st;
                    if ((st >> 32) == 2ULL) break;
                    p--;
                }
                atomicExch(&g_tile_state[tile], (2ULL << 32) | (unsigned)(pre + agg));
                sprefix = pre;
            }
        }
        __syncthreads();
        if (i < NN) {
            int rp = sprefix + incl - v;   // exclusive
            g_rowptr[i] = rp;
            g_cursor[i] = rp;
        }
        if (tile == 0 && t == 0) g_rowptr[NN] = NCSR;
    } else {
        int i = (blockIdx.x - NSCAN) * 512 + threadIdx.x;   // quad of 4 floats
        if (i < NN * (NF / 4)) {
            float4 v = ((const float4*)x)[i];
            __half2 a = __floats2half2_rn(v.x * 0.5f, v.y * 0.5f);
            __half2 b = __floats2half2_rn(v.z * 0.5f, v.w * 0.5f);
            *(uint2*)&g_hh[(size_t)i * 2] =
                make_uint2(*(unsigned*)&a, *(unsigned*)&b);
        }
    }
}

// ---------------- L2b: exclusive scan of 1024 degree bins (1 block) --------
__global__ void __launch_bounds__(1024) k_degscan() {
    __shared__ int s[NDEG];
    int t = threadIdx.x;
    int v = g_degcnt[t];
    s[t] = v;
    __syncthreads();
    for (int off = 1; off < NDEG; off <<= 1) {
        int add = (t >= off) ? s[t - off] : 0;
        __syncthreads();
        s[t] += add;
        __syncthreads();
    }
    g_degoff[t] = s[t] - v;   // exclusive
}

// ---------------- L3: scatter edges + self-loops + task build + re-zero ----
__global__ void k_scatter(const int* __restrict__ ei) {
    int e = blockIdx.x * blockDim.x + threadIdx.x;
    if (e < NE) {
        int r = clampN(ei[e]);
        int c = clampN(ei[NE + e]);
        int pos = atomicAdd(&g_cursor[r], 1);
        __half2 wh = __float2half2_rn(g_dinv[r] * g_dinv[c]);
        g_csr[pos] = make_int2(c * 32, *reinterpret_cast<int*>(&wh));
    }
    if (e < NN) {
        // self-loop edge: weight dinv[e]^2
        float dr = g_dinv[e];
        int pos = atomicAdd(&g_cursor[e], 1);
        __half2 wh = __float2half2_rn(dr * dr);
        g_csr[pos] = make_int2(e * 32, *reinterpret_cast<int*>(&wh));
        // degree-sorted task descriptor
        int d = g_cnt[e];
        int p = atomicAdd(&g_degoff[min(d, NDEG - 1)], 1);
        int start = g_rowptr[e];
        int len   = g_rowptr[e + 1] - start;   // = deg+1
        g_task[p] = make_int4(start, len, e * 32, 0);
        g_cnt[e] = 0;
    }
}

// ---------------- SPMM: h_{it+1} = A_norm h_it ------------------------------
// 4 rows/warp (degree-sorted tasks), 8-lane group per row, lane = 8 features.
// Prologue = ONE broadcast int4 load per group; self-loops are CSR edges.
__global__ void __launch_bounds__(256) k_spmm(int it) {
    const size_t NN32 = (size_t)NN * (NF / 2);
    const __half2* __restrict__ hin = g_hh + (size_t)it * NN32;
    __half2* __restrict__ hout      = g_hh + (size_t)(it + 1) * NN32;

    __shared__ int2 se[8][4][17];    // [warp][group][slot], padded

    int lane = threadIdx.x & 31;
    int wid  = threadIdx.x >> 5;
    int g    = lane >> 3;            // group 0..3
    int li   = lane & 7;             // lane in group

    int4 task = __ldg(&g_task[(blockIdx.x * 8 + wid) * 4 + g]);  // NN div by 32
    int start = task.x;
    int len   = task.y;
    int end   = start + len;
    int row32 = task.z;

    float accf[8] = {0.f, 0.f, 0.f, 0.f, 0.f, 0.f, 0.f, 0.f};

    // uniform loop bound over the 4 groups (sorted rows -> nearly equal)
    int m1   = max(len, __shfl_xor_sync(0xffffffffu, len, 8));
    int mlen = max(m1,  __shfl_xor_sync(0xffffffffu, m1, 16));

    const __half2 z2 = __float2half2_rn(0.f);

    for (int b = 0; b < mlen; b += 16) {
        int idx0 = start + b + li;
        int idx1 = idx0 + 8;
        int2 e0 = (idx0 < end) ? g_csr[idx0] : make_int2(0, 0);
        int2 e1 = (idx1 < end) ? g_csr[idx1] : make_int2(0, 0);
        se[wid][g][li]     = e0;
        se[wid][g][li + 8] = e1;
        __syncwarp();

        __half2 a0 = z2, a1 = z2, a2 = z2, a3 = z2;   // even slots
        __half2 c0 = z2, c1 = z2, c2 = z2, c3 = z2;   // odd slots
#pragma unroll
        for (int j = 0; j < 16; j++) {                // fixed trip: batched LDGs
            int2    ej = se[wid][g][j];
            __half2 wj = *reinterpret_cast<__half2*>(&ej.y);
            uint4   t  = __ldg((const uint4*)(hin + ej.x + li * 4));
            __half2 t0 = *(__half2*)&t.x, t1 = *(__half2*)&t.y;
            __half2 t2 = *(__half2*)&t.z, t3 = *(__half2*)&t.w;
            if (j & 1) {
                c0 = __hfma2(wj, t0, c0); c1 = __hfma2(wj, t1, c1);
                c2 = __hfma2(wj, t2, c2); c3 = __hfma2(wj, t3, c3);
            } else {
                a0 = __hfma2(wj, t0, a0); a1 = __hfma2(wj, t1, a1);
                a2 = __hfma2(wj, t2, a2); a3 = __hfma2(wj, t3, a3);
            }
        }
        __syncwarp();

        float2 s0 = __half22float2(__hadd2(a0, c0));
        float2 s1 = __half22float2(__hadd2(a1, c1));
        float2 s2 = __half22float2(__hadd2(a2, c2));
        float2 s3 = __half22float2(__hadd2(a3, c3));
        accf[0] += s0.x; accf[1] += s0.y;
        accf[2] += s1.x; accf[3] += s1.y;
        accf[4] += s2.x; accf[5] += s2.y;
        accf[6] += s3.x; accf[7] += s3.y;
    }

    __half2 r0 = __floats2half2_rn(accf[0], accf[1]);
    __half2 r1 = __floats2half2_rn(accf[2], accf[3]);
    __half2 r2 = __floats2half2_rn(accf[4], accf[5]);
    __half2 r3 = __floats2half2_rn(accf[6], accf[7]);
    uint4 o;
    o.x = *(unsigned*)&r0; o.y = *(unsigned*)&r1;
    o.z = *(unsigned*)&r2; o.w = *(unsigned*)&r3;
    *(uint4*)(hout + row32 + li * 4) = o;
}

// ---------------- fused MLP on tensor cores (wmma m16n16k16, f32 accum) ----
#define LDA 72   // fp16 lds (mult of 8)
#define LDB 48   // W2 cols padded
__global__ void __launch_bounds__(256) k_mlp(const float* __restrict__ W1,
                                             const float* __restrict__ b1,
                                             const float* __restrict__ W2,
                                             const float* __restrict__ b2,
                                             float* __restrict__ out) {
    __shared__ __align__(16) __half AsH[32 * LDA];    // 4.6 KB
    __shared__ __align__(16) __half W1cH[64 * LDA];   // 9.2 KB
    __shared__ __align__(16) float  HsF[32 * LDA];    // 9.2 KB
    __shared__ __align__(16) __half HsH[32 * LDA];    // 4.6 KB
    __shared__ __align__(16) __half W2cH[64 * LDB];   // 6.1 KB
    __shared__ __align__(16) float  OutF[32 * LDB];   // 6.1 KB

    int tid = threadIdx.x;
    int wid = tid >> 5;
    int rb  = blockIdx.x * 32;        // NN divisible by 32

    const float inv = 1.0f / (NITER + 1);
    const size_t NN32 = (size_t)NN * (NF / 2);
    for (int l = tid; l < 32 * 16; l += 256) {   // quads of 4 feats
        int rr = l >> 4, q = l & 15;
        float4 s = make_float4(0.f, 0.f, 0.f, 0.f);
#pragma unroll
        for (int b = 0; b <= NITER; b++) {
            const uint2* hb = (const uint2*)(g_hh + (size_t)b * NN32);
            uint2 v = __ldg(&hb[(size_t)(rb + rr) * 16 + q]);
            float2 f0 = __half22float2(*(__half2*)&v.x);
            float2 f1 = __half22float2(*(__half2*)&v.y);
            s.x += f0.x; s.y += f0.y; s.z += f1.x; s.w += f1.y;
        }
        __half2 p0 = __floats2half2_rn(s.x * inv, s.y * inv);
        __half2 p1 = __floats2half2_rn(s.z * inv, s.w * inv);
        *(uint2*)&AsH[rr * LDA + q * 4] =
            make_uint2(*(unsigned*)&p0, *(unsigned*)&p1);
    }

    wmma::fragment<wmma::accumulator, 16, 16, 16, float> ofrag;
    int omi = wid / 3, oni = wid % 3;   // warps 0..5: out tile (omi, oni)
    if (wid < 6) wmma::fill_fragment(ofrag, 0.f);

    for (int c = 0; c < 4; c++) {
        __syncthreads();
        for (int l = tid; l < 64 * 64; l += 256) {
            int kk = l >> 6, j = l & 63;
            W1cH[kk * LDA + j] = __float2half(__ldg(&W1[kk * NH + c * 64 + j]));
        }
        for (int l = tid; l < 64 * LDB; l += 256) {
            int kk = l / LDB, n = l % LDB;
            W2cH[kk * LDB + n] =
                (n < NC) ? __float2half(__ldg(&W2[(c * 64 + kk) * NC + n]))
                         : __half(0.f);
        }
        __syncthreads();

        {
            int mi = wid >> 2, ni = wid & 3;
            wmma::fragment<wmma::accumulator, 16, 16, 16, float> hfrag;
            wmma::fill_fragment(hfrag, 0.f);
#pragma unroll
            for (int k = 0; k < 4; k++) {
                wmma::fragment<wmma::matrix_a, 16, 16, 16, __half, wmma::row_major> af;
                wmma::fragment<wmma::matrix_b, 16, 16, 16, __half, wmma::row_major> bf;
                wmma::load_matrix_sync(af, &AsH[mi * 16 * LDA + k * 16], LDA);
                wmma::load_matrix_sync(bf, &W1cH[k * 16 * LDA + ni * 16], LDA);
                wmma::mma_sync(hfrag, af, bf, hfrag);
            }
            wmma::store_matrix_sync(&HsF[mi * 16 * LDA + ni * 16], hfrag, LDA,
                                    wmma::mem_row_major);
        }
        __syncthreads();

        for (int l = tid; l < 32 * 64; l += 256) {
            int r = l >> 6, j = l & 63;
            float v = HsF[r * LDA + j] + __ldg(&b1[c * 64 + j]);
            HsH[r * LDA + j] = __float2half(fmaxf(v, 0.f));
        }
        __syncthreads();

        if (wid < 6) {
#pragma unroll
            for (int k = 0; k < 4; k++) {
                wmma::fragment<wmma::matrix_a, 16, 16, 16, __half, wmma::row_major> af;
                wmma::fragment<wmma::matrix_b, 16, 16, 16, __half, wmma::row_major> bf;
                wmma::load_matrix_sync(af, &HsH[omi * 16 * LDA + k * 16], LDA);
                wmma::load_matrix_sync(bf, &W2cH[k * 16 * LDB + oni * 16], LDB);
                wmma::mma_sync(ofrag, af, bf, ofrag);
            }
        }
    }

    __syncthreads();
    if (wid < 6)
        wmma::store_matrix_sync(&OutF[omi * 16 * LDB + oni * 16], ofrag, LDB,
                                wmma::mem_row_major);
    __syncthreads();

    for (int l = tid; l < 32 * NC; l += 256) {
        int r = l / NC, n = l - r * NC;
        out[(size_t)(rb + r) * NC + n] = OutF[r * LDB + n] + __ldg(&b2[n]);
    }
}

// ---------------- launch ----------------
extern "C" void kernel_launch(void* const* d_in, const int* in_sizes, int n_in,
                              void* d_out, int out_size) {
    const float* x   = (const float*)d_in[0];
    const int*   ei  = (const int*)d_in[1];   // int32 (JAX demotes int64)
    const float* W1  = (const float*)d_in[2];
    const float* b1  = (const float*)d_in[3];
    const float* W2  = (const float*)d_in[4];
    const float* b2  = (const float*)d_in[5];
    float*       out = (float*)d_out;

    int init_blocks = (NN * (NF / 4) + 511) / 512;   // 3125

    k_hist<<<(NE + 255) / 256, 256>>>(ei);                     // launch 1
    k_scan_init<<<NSCAN + init_blocks, 512>>>(x);              // launch 2
    k_degscan<<<1, NDEG>>>();                                  // launch 3
    k_scatter<<<(NE + 255) / 256, 256>>>(ei);                  // launch 4

    for (int it = 0; it < NITER; it++)                         // launches 5..12
        k_spmm<<<NN / 32, 256>>>(it);

    k_mlp<<<NN / 32, 256>>>(W1, b1, W2, b2, out);              // launch 13
}